// round 15
// baseline (speedup 1.0000x reference)
#include <cuda_runtime.h>
#include <cuda_fp16.h>
#include <math_constants.h>

#define N_NODES 100000
#define N_EDGES 1600000
#define N_GRAPHS 64
#define EPSV 1e-16f

// ---------------- scratch (device globals; no allocations) ----------------
__device__ float  g_q1[N_NODES * 64];
__device__ __half g_kv1h[N_NODES * 128];   // interleaved: [4k|4v] per 8-half group
__device__ float  g_s1[N_NODES * 64];
__device__ float  g_h1[N_NODES * 64];

__device__ float  g_q2[N_NODES * 128];     // after layer-2 edge pass, holds h2
__device__ __align__(32) __half g_kv2h[N_NODES * 256];   // interleaved: [8k|8v]
__device__ float  g_s2[N_NODES * 128];

__device__ float g_pool[N_GRAPHS * 128];

// CSR + degree-sorted schedule
__device__ int g_deg[N_NODES];
__device__ int g_rowptr[N_NODES + 1];
__device__ int g_cursor[N_NODES];
__device__ int g_esrc[N_EDGES];
__device__ int g_dbin[64];
__device__ int g_dcur[64];
__device__ int g_perm[N_NODES];

// ---------------- helpers ----------------
__device__ __forceinline__ void atomicMaxF(float* addr, float val) {
    if (val >= 0.0f)
        atomicMax((int*)addr, __float_as_int(val));
    else
        atomicMin((unsigned int*)addr, __float_as_uint(val));
}

__device__ __forceinline__ unsigned long long pack_f2(float a, float b) {
    unsigned long long r;
    asm("mov.b64 %0, {%1, %2};" : "=l"(r) : "f"(a), "f"(b));
    return r;
}
__device__ __forceinline__ void ffma2(unsigned long long& d,
                                      unsigned long long a, unsigned long long b) {
    asm("fma.rn.f32x2 %0, %1, %2, %0;" : "+l"(d) : "l"(a), "l"(b));
}
__device__ __forceinline__ void unpack_f2(unsigned long long d, float& x, float& y) {
    asm("mov.b64 {%0, %1}, %2;" : "=f"(x), "=f"(y) : "l"(d));
}

// 256-bit global load (sm_100+)
__device__ __forceinline__ void ldg_v8(const void* p, uint4& a, uint4& b) {
    asm("ld.global.nc.v8.b32 {%0,%1,%2,%3,%4,%5,%6,%7}, [%8];"
        : "=r"(a.x), "=r"(a.y), "=r"(a.z), "=r"(a.w),
          "=r"(b.x), "=r"(b.y), "=r"(b.z), "=r"(b.w)
        : "l"(p));
}

// decode one uint4 (8 halves) -> two float4
__device__ __forceinline__ void dec_h8(uint4 u, float4& lo, float4& hi) {
    float2 a = __half22float2(*reinterpret_cast<const __half2*>(&u.x));
    float2 b = __half22float2(*reinterpret_cast<const __half2*>(&u.y));
    float2 c = __half22float2(*reinterpret_cast<const __half2*>(&u.z));
    float2 d = __half22float2(*reinterpret_cast<const __half2*>(&u.w));
    lo = make_float4(a.x, a.y, b.x, b.y);
    hi = make_float4(c.x, c.y, d.x, d.y);
}
__device__ __forceinline__ void dec_kv(uint4 u, float4& kk, float4& vv) {
    dec_h8(u, kk, vv);
}

// ================= CSR build =================
__global__ void k_zero_meta() {
    int i = blockIdx.x * blockDim.x + threadIdx.x;
    if (i < N_NODES) g_deg[i] = 0;
    if (i < 64) g_dbin[i] = 0;
}

__global__ void k_hist(const int* __restrict__ ei) {
    int t = blockIdx.x * blockDim.x + threadIdx.x;
    if (t >= N_EDGES / 4) return;
    int4 d4 = __ldg((const int4*)(ei + N_EDGES) + t);
    atomicAdd(&g_deg[d4.x], 1);
    atomicAdd(&g_deg[d4.y], 1);
    atomicAdd(&g_deg[d4.z], 1);
    atomicAdd(&g_deg[d4.w], 1);
}

__global__ void k_scan() {
    __shared__ int s_sums[1024];
    const int CH = 98;
    int t = threadIdx.x;
    int base = t * CH;
    int sum = 0;
    for (int i = 0; i < CH; i++) {
        int idx = base + i;
        if (idx < N_NODES) sum += g_deg[idx];
    }
    s_sums[t] = sum;
    __syncthreads();
    for (int d = 1; d < 1024; d <<= 1) {
        int v = (t >= d) ? s_sums[t - d] : 0;
        __syncthreads();
        s_sums[t] += v;
        __syncthreads();
    }
    int run = s_sums[t] - sum;
    for (int i = 0; i < CH; i++) {
        int idx = base + i;
        if (idx < N_NODES) {
            g_rowptr[idx] = run;
            g_cursor[idx] = run;
            run += g_deg[idx];
        }
    }
    if (t == 1023) g_rowptr[N_NODES] = N_EDGES;
}

__global__ void k_scatter(const int* __restrict__ ei) {
    int t = blockIdx.x * blockDim.x + threadIdx.x;
    if (t >= N_EDGES / 4) return;
    int4 s4 = __ldg((const int4*)ei + t);
    int4 d4 = __ldg((const int4*)(ei + N_EDGES) + t);
    g_esrc[atomicAdd(&g_cursor[d4.x], 1)] = s4.x;
    g_esrc[atomicAdd(&g_cursor[d4.y], 1)] = s4.y;
    g_esrc[atomicAdd(&g_cursor[d4.z], 1)] = s4.z;
    g_esrc[atomicAdd(&g_cursor[d4.w], 1)] = s4.w;
}

// ================= degree counting sort (64 bins) =================
__global__ void k_degbin() {
    int i = blockIdx.x * blockDim.x + threadIdx.x;
    if (i < N_NODES) atomicAdd(&g_dbin[min(g_deg[i], 63)], 1);
}

__global__ void k_degscan() {
    __shared__ int s[64];
    int t = threadIdx.x;
    s[t] = g_dbin[t];
    __syncthreads();
    if (t == 0) {
        int run = 0;
        for (int i = 0; i < 64; i++) { int c = s[i]; s[i] = run; run += c; }
    }
    __syncthreads();
    g_dcur[t] = s[t];
}

__global__ void k_degscatter() {
    int i = blockIdx.x * blockDim.x + threadIdx.x;
    if (i >= N_NODES) return;
    int pos = atomicAdd(&g_dcur[min(g_deg[i], 63)], 1);
    g_perm[pos] = i;
}

// ---------------- layer 1: node QKV + skip ----------------
__global__ void k_l1_qkv(const float* __restrict__ x,
                         const float* __restrict__ Wq, const float* __restrict__ bq,
                         const float* __restrict__ Wk, const float* __restrict__ bk,
                         const float* __restrict__ Wv, const float* __restrict__ bv,
                         const float* __restrict__ Ws, const float* __restrict__ bs) {
    int idx = blockIdx.x * blockDim.x + threadIdx.x;
    if (idx >= N_NODES * 64) return;
    int n = idx >> 6;
    int j = idx & 63;
    float x0 = __ldg(x + n * 3 + 0);
    float x1 = __ldg(x + n * 3 + 1);
    float x2 = __ldg(x + n * 3 + 2);

    float q = __ldg(bq + j) + x0 * __ldg(Wq + j) + x1 * __ldg(Wq + 64 + j) + x2 * __ldg(Wq + 128 + j);
    float k = __ldg(bk + j) + x0 * __ldg(Wk + j) + x1 * __ldg(Wk + 64 + j) + x2 * __ldg(Wk + 128 + j);
    float v = __ldg(bv + j) + x0 * __ldg(Wv + j) + x1 * __ldg(Wv + 64 + j) + x2 * __ldg(Wv + 128 + j);
    float s = __ldg(bs + j) + x0 * __ldg(Ws + j) + x1 * __ldg(Ws + 64 + j) + x2 * __ldg(Ws + 128 + j);

    g_q1[idx] = q;
    int c = j >> 2, r = j & 3;
    g_kv1h[(size_t)n * 128 + c * 8 + r]     = __float2half(k);
    g_kv1h[(size_t)n * 128 + c * 8 + 4 + r] = __float2half(v);
    g_s1[idx] = s;
}

// ================= layer-1 fused edge pass: 2 (degree-matched) nodes/warp ==
__global__ void k_edge1() {
    const float RSC = 0.17677669529663687f;  // 1/sqrt(32)
    int gw = (blockIdx.x * blockDim.x + threadIdx.x) >> 5;
    int lane = threadIdx.x & 31;
    int half = lane >> 4;
    int hl = lane & 15;
    int pid = gw * 2 + half;
    if (pid >= N_NODES) return;              // N_NODES even -> warp uniform
    int n = __ldg(&g_perm[pid]);
    unsigned mask = half ? 0xFFFF0000u : 0x0000FFFFu;

    int beg = __ldg(&g_rowptr[n]);
    int end = __ldg(&g_rowptr[n + 1]);

    const uint4* kvb = (const uint4*)g_kv1h;  // 16 uint4 per row
    float4 qa = *(const float4*)(g_q1 + (size_t)n * 64 + hl * 4);
    float4 acc = make_float4(0.f, 0.f, 0.f, 0.f);
    float ssum = 0.0f;

    int idx = beg;
    for (; idx + 2 <= end; idx += 2) {
        int s0 = __ldg(&g_esrc[idx]);
        int s1 = __ldg(&g_esrc[idx + 1]);
        uint4 u0 = __ldg(kvb + (size_t)s0 * 16 + hl);
        uint4 u1 = __ldg(kvb + (size_t)s1 * 16 + hl);
        float4 k0, v0, k1, v1;
        dec_kv(u0, k0, v0);
        dec_kv(u1, k1, v1);
        float p0 = qa.x * k0.x + qa.y * k0.y + qa.z * k0.z + qa.w * k0.w;
        float p1 = qa.x * k1.x + qa.y * k1.y + qa.z * k1.z + qa.w * k1.w;
#pragma unroll
        for (int d = 4; d >= 1; d >>= 1) {
            p0 += __shfl_xor_sync(mask, p0, d);
            p1 += __shfl_xor_sync(mask, p1, d);
        }
        float e0 = __expf(p0 * RSC);
        float e1 = __expf(p1 * RSC);
        ssum += e0 + e1;
        acc.x += e0 * v0.x + e1 * v1.x;
        acc.y += e0 * v0.y + e1 * v1.y;
        acc.z += e0 * v0.z + e1 * v1.z;
        acc.w += e0 * v0.w + e1 * v1.w;
    }
    for (; idx < end; idx++) {
        int s0 = __ldg(&g_esrc[idx]);
        uint4 u0 = __ldg(kvb + (size_t)s0 * 16 + hl);
        float4 k0, v0;
        dec_kv(u0, k0, v0);
        float p0 = qa.x * k0.x + qa.y * k0.y + qa.z * k0.z + qa.w * k0.w;
#pragma unroll
        for (int d = 4; d >= 1; d >>= 1) p0 += __shfl_xor_sync(mask, p0, d);
        float e0 = __expf(p0 * RSC);
        ssum += e0;
        acc.x += e0 * v0.x; acc.y += e0 * v0.y;
        acc.z += e0 * v0.z; acc.w += e0 * v0.w;
    }
    float rh = 1.0f / (ssum + EPSV);
    float4 sk = *(const float4*)(g_s1 + (size_t)n * 64 + hl * 4);
    float4 o;
    o.x = fmaxf(acc.x * rh + sk.x, 0.0f);
    o.y = fmaxf(acc.y * rh + sk.y, 0.0f);
    o.z = fmaxf(acc.z * rh + sk.z, 0.0f);
    o.w = fmaxf(acc.w * rh + sk.w, 0.0f);
    *(float4*)(g_h1 + (size_t)n * 64 + hl * 4) = o;
}

// ================= layer-2 fused edge pass: 2 (degree-matched) nodes/warp ==
__global__ void k_edge2() {
    const float RSC = 0.125f;  // 1/sqrt(64)
    int gw = (blockIdx.x * blockDim.x + threadIdx.x) >> 5;
    int lane = threadIdx.x & 31;
    int half = lane >> 4;
    int hl = lane & 15;
    int pid = gw * 2 + half;
    if (pid >= N_NODES) return;
    int n = __ldg(&g_perm[pid]);
    unsigned mask = half ? 0xFFFF0000u : 0x0000FFFFu;

    int beg = __ldg(&g_rowptr[n]);
    int end = __ldg(&g_rowptr[n + 1]);

    const uint4* kvb = (const uint4*)g_kv2h;  // 32 uint4 per row
    float4 qa = *(const float4*)(g_q2 + (size_t)n * 128 + hl * 8);
    float4 qb = *(const float4*)(g_q2 + (size_t)n * 128 + hl * 8 + 4);
    float4 accA = make_float4(0.f, 0.f, 0.f, 0.f);
    float4 accB = make_float4(0.f, 0.f, 0.f, 0.f);
    float ssum = 0.0f;

    int idx = beg;
    for (; idx + 2 <= end; idx += 2) {
        int s0 = __ldg(&g_esrc[idx]);
        int s1 = __ldg(&g_esrc[idx + 1]);
        uint4 uk0, uv0, uk1, uv1;
        ldg_v8(kvb + (size_t)s0 * 32 + hl * 2, uk0, uv0);
        ldg_v8(kvb + (size_t)s1 * 32 + hl * 2, uk1, uv1);
        float4 k0a, k0b, k1a, k1b;
        dec_h8(uk0, k0a, k0b);
        dec_h8(uk1, k1a, k1b);
        float p0 = qa.x * k0a.x + qa.y * k0a.y + qa.z * k0a.z + qa.w * k0a.w
                 + qb.x * k0b.x + qb.y * k0b.y + qb.z * k0b.z + qb.w * k0b.w;
        float p1 = qa.x * k1a.x + qa.y * k1a.y + qa.z * k1a.z + qa.w * k1a.w
                 + qb.x * k1b.x + qb.y * k1b.y + qb.z * k1b.z + qb.w * k1b.w;
#pragma unroll
        for (int d = 4; d >= 1; d >>= 1) {
            p0 += __shfl_xor_sync(mask, p0, d);
            p1 += __shfl_xor_sync(mask, p1, d);
        }
        float e0 = __expf(p0 * RSC);
        float e1 = __expf(p1 * RSC);
        ssum += e0 + e1;
        float4 v0a, v0b, v1a, v1b;
        dec_h8(uv0, v0a, v0b);
        dec_h8(uv1, v1a, v1b);
        accA.x += e0 * v0a.x + e1 * v1a.x;
        accA.y += e0 * v0a.y + e1 * v1a.y;
        accA.z += e0 * v0a.z + e1 * v1a.z;
        accA.w += e0 * v0a.w + e1 * v1a.w;
        accB.x += e0 * v0b.x + e1 * v1b.x;
        accB.y += e0 * v0b.y + e1 * v1b.y;
        accB.z += e0 * v0b.z + e1 * v1b.z;
        accB.w += e0 * v0b.w + e1 * v1b.w;
    }
    for (; idx < end; idx++) {
        int s0 = __ldg(&g_esrc[idx]);
        uint4 uk0, uv0;
        ldg_v8(kvb + (size_t)s0 * 32 + hl * 2, uk0, uv0);
        float4 k0a, k0b;
        dec_h8(uk0, k0a, k0b);
        float p0 = qa.x * k0a.x + qa.y * k0a.y + qa.z * k0a.z + qa.w * k0a.w
                 + qb.x * k0b.x + qb.y * k0b.y + qb.z * k0b.z + qb.w * k0b.w;
#pragma unroll
        for (int d = 4; d >= 1; d >>= 1) p0 += __shfl_xor_sync(mask, p0, d);
        float e0 = __expf(p0 * RSC);
        ssum += e0;
        float4 v0a, v0b;
        dec_h8(uv0, v0a, v0b);
        accA.x += e0 * v0a.x; accA.y += e0 * v0a.y;
        accA.z += e0 * v0a.z; accA.w += e0 * v0a.w;
        accB.x += e0 * v0b.x; accB.y += e0 * v0b.y;
        accB.z += e0 * v0b.z; accB.w += e0 * v0b.w;
    }
    float rh = 1.0f / (ssum + EPSV);
    float4 skA = *(const float4*)(g_s2 + (size_t)n * 128 + hl * 8);
    float4 skB = *(const float4*)(g_s2 + (size_t)n * 128 + hl * 8 + 4);
    float4 oA, oB;
    oA.x = fmaxf(accA.x * rh + skA.x, 0.0f);
    oA.y = fmaxf(accA.y * rh + skA.y, 0.0f);
    oA.z = fmaxf(accA.z * rh + skA.z, 0.0f);
    oA.w = fmaxf(accA.w * rh + skA.w, 0.0f);
    oB.x = fmaxf(accB.x * rh + skB.x, 0.0f);
    oB.y = fmaxf(accB.y * rh + skB.y, 0.0f);
    oB.z = fmaxf(accB.z * rh + skB.z, 0.0f);
    oB.w = fmaxf(accB.w * rh + skB.w, 0.0f);
    *(float4*)(g_q2 + (size_t)n * 128 + hl * 8) = oA;      // h2 in place
    *(float4*)(g_q2 + (size_t)n * 128 + hl * 8 + 4) = oB;
}

// ---------------- layer 2 GEMM: f32x2 packed, smem-staged h1 ----------------
__global__ void k_l2_qkv(const float* __restrict__ Wq, const float* __restrict__ bq,
                         const float* __restrict__ Wk, const float* __restrict__ bk,
                         const float* __restrict__ Wv, const float* __restrict__ bv,
                         const float* __restrict__ Ws, const float* __restrict__ bs) {
    __shared__ __align__(16) float shT[64][20];
    int tid = threadIdx.x;
    int nb = blockIdx.x * 16;

    {
        float4 f = *(const float4*)(g_h1 + (size_t)nb * 64 + tid * 4);
        int node = tid >> 4;
        int i0 = (tid & 15) * 4;
        shT[i0 + 0][node] = f.x;
        shT[i0 + 1][node] = f.y;
        shT[i0 + 2][node] = f.z;
        shT[i0 + 3][node] = f.w;
    }
    __syncthreads();

    int mat = blockIdx.y * 2 + (tid >> 7);   // 0..3
    int j = tid & 127;
    const float* W; const float* B;
    if (mat == 0)      { W = Wq; B = bq; }
    else if (mat == 1) { W = Wk; B = bk; }
    else if (mat == 2) { W = Wv; B = bv; }
    else               { W = Ws; B = bs; }

    float bj = __ldg(B + j);
    unsigned long long acc[8];
#pragma unroll
    for (int r = 0; r < 8; r++) acc[r] = pack_f2(bj, bj);

    const unsigned long long* shT64 = (const unsigned long long*)&shT[0][0];
    for (int i = 0; i < 64; i++) {
        float w = __ldg(W + i * 128 + j);
        unsigned long long wp = pack_f2(w, w);
        int rb = i * 10;                     // 20 floats = 10 ull per row
#pragma unroll
        for (int r4 = 0; r4 < 4; r4++) {
            unsigned long long hp0 = shT64[rb + r4 * 2 + 0];
            unsigned long long hp1 = shT64[rb + r4 * 2 + 1];
            ffma2(acc[2 * r4 + 0], hp0, wp);
            ffma2(acc[2 * r4 + 1], hp1, wp);
        }
    }
    if (mat == 0 || mat == 3) {
        float* Of = (mat == 0) ? g_q2 : g_s2;
#pragma unroll
        for (int r = 0; r < 8; r++) {
            float o0, o1;
            unpack_f2(acc[r], o0, o1);
            Of[(size_t)(nb + 2 * r + 0) * 128 + j] = o0;
            Of[(size_t)(nb + 2 * r + 1) * 128 + j] = o1;
        }
    } else {
        // interleaved kv2 [8k|8v]: k col j -> (j>>3)*16 + (j&7); v -> +8
        int jj = ((j >> 3) * 16) + (j & 7) + ((mat == 2) ? 8 : 0);
#pragma unroll
        for (int r = 0; r < 8; r++) {
            float o0, o1;
            unpack_f2(acc[r], o0, o1);
            g_kv2h[(size_t)(nb + 2 * r + 0) * 256 + jj] = __float2half(o0);
            g_kv2h[(size_t)(nb + 2 * r + 1) * 256 + jj] = __float2half(o1);
        }
    }
}

// ---------------- pool init ----------------
__global__ void k_init_pool() {
    int i = blockIdx.x * blockDim.x + threadIdx.x;
    if (i < N_GRAPHS * 128) g_pool[i] = -CUDART_INF_F;
}

// ---------------- pool: run-length max over sorted batch (32 nodes/block) --
__global__ void k_pool(const int* __restrict__ batch) {
    int j = threadIdx.x;
    int n0 = blockIdx.x * 32;
    float cur = -CUDART_INF_F;
    int curg = __ldg(batch + n0);
#pragma unroll 4
    for (int r = 0; r < 32; r++) {
        int n = n0 + r;
        int g = __ldg(batch + n);
        if (g != curg) {
            atomicMaxF(&g_pool[curg * 128 + j], cur);
            cur = -CUDART_INF_F;
            curg = g;
        }
        cur = fmaxf(cur, g_q2[(size_t)n * 128 + j]);   // h2 lives in g_q2
    }
    atomicMaxF(&g_pool[curg * 128 + j], cur);
}

// ---------------- MLP head (single block) ----------------
__global__ void k_mlp(const float* __restrict__ W1, const float* __restrict__ b1,
                      const float* __restrict__ W2, const float* __restrict__ b2,
                      const float* __restrict__ W3, const float* __restrict__ b3,
                      float* __restrict__ out) {
    __shared__ float s_lat[64 * 32];
    __shared__ float s_h[64 * 128];
    int tid = threadIdx.x;
    for (int idx = tid; idx < 64 * 32; idx += blockDim.x) {
        int g = idx >> 5, j = idx & 31;
        float a = __ldg(b1 + j);
        for (int i = 0; i < 128; i++) a += g_pool[g * 128 + i] * __ldg(W1 + i * 32 + j);
        a = fmaxf(a, 0.0f);
        s_lat[idx] = a;
        out[2560 + idx] = a;
    }
    __syncthreads();
    for (int idx = tid; idx < 64 * 128; idx += blockDim.x) {
        int g = idx >> 7, j = idx & 127;
        float a = __ldg(b2 + j);
        for (int i = 0; i < 32; i++) a += s_lat[g * 32 + i] * __ldg(W2 + i * 128 + j);
        s_h[idx] = fmaxf(a, 0.0f);
    }
    __syncthreads();
    for (int idx = tid; idx < 64 * 40; idx += blockDim.x) {
        int g = idx / 40, c = idx - g * 40;
        float a = __ldg(b3 + c);
        for (int i = 0; i < 128; i++) a += s_h[g * 128 + i] * __ldg(W3 + i * 40 + c);
        out[idx] = a;
    }
}

// ---------------- launch ----------------
extern "C" void kernel_launch(void* const* d_in, const int* in_sizes, int n_in,
                              void* d_out, int out_size) {
    const float* x     = (const float*)d_in[0];
    const int*   ei    = (const int*)d_in[1];
    const int*   batch = (const int*)d_in[2];
    const float *Wq1 = (const float*)d_in[3],  *bq1 = (const float*)d_in[4];
    const float *Wk1 = (const float*)d_in[5],  *bk1 = (const float*)d_in[6];
    const float *Wv1 = (const float*)d_in[7],  *bv1 = (const float*)d_in[8];
    const float *Ws1 = (const float*)d_in[9],  *bs1 = (const float*)d_in[10];
    const float *Wq2 = (const float*)d_in[11], *bq2 = (const float*)d_in[12];
    const float *Wk2 = (const float*)d_in[13], *bk2 = (const float*)d_in[14];
    const float *Wv2 = (const float*)d_in[15], *bv2 = (const float*)d_in[16];
    const float *Ws2 = (const float*)d_in[17], *bs2 = (const float*)d_in[18];
    const float *W1  = (const float*)d_in[19], *b1  = (const float*)d_in[20];
    const float *W2  = (const float*)d_in[21], *b2  = (const float*)d_in[22];
    const float *W3  = (const float*)d_in[23], *b3  = (const float*)d_in[24];
    float* out = (float*)d_out;

    // one-time side streams + events (host-side resources only)
    static cudaStream_t s_side = nullptr, s_side2 = nullptr;
    static cudaEvent_t ev_fork = nullptr, ev_hist = nullptr;
    static cudaEvent_t ev_join = nullptr, ev_join2 = nullptr;
    if (s_side == nullptr) {
        cudaStreamCreateWithFlags(&s_side, cudaStreamNonBlocking);
        cudaStreamCreateWithFlags(&s_side2, cudaStreamNonBlocking);
        cudaEventCreateWithFlags(&ev_fork, cudaEventDisableTiming);
        cudaEventCreateWithFlags(&ev_hist, cudaEventDisableTiming);
        cudaEventCreateWithFlags(&ev_join, cudaEventDisableTiming);
        cudaEventCreateWithFlags(&ev_join2, cudaEventDisableTiming);
    }

    const int PAIR_NODE_BLOCKS = ((N_NODES / 2) * 32 + 255) / 256;  // 2 nodes/warp

    // fork: CSR build on side stream (meta zeroed at tail of previous call;
    // device globals start zeroed on module load for the first call)
    cudaEventRecord(ev_fork, 0);
    cudaStreamWaitEvent(s_side, ev_fork, 0);
    k_hist<<<(N_EDGES / 4 + 255) / 256, 256, 0, s_side>>>(ei);
    cudaEventRecord(ev_hist, s_side);
    k_scan<<<1, 1024, 0, s_side>>>();
    k_scatter<<<(N_EDGES / 4 + 255) / 256, 256, 0, s_side>>>(ei);
    cudaEventRecord(ev_join, s_side);

    // degree counting sort on second side stream, concurrent with scan/scatter
    cudaStreamWaitEvent(s_side2, ev_hist, 0);
    k_degbin<<<(N_NODES + 255) / 256, 256, 0, s_side2>>>();
    k_degscan<<<1, 64, 0, s_side2>>>();
    k_degscatter<<<(N_NODES + 255) / 256, 256, 0, s_side2>>>();
    cudaEventRecord(ev_join2, s_side2);

    // main stream: node-parallel work that doesn't need the CSR
    k_l1_qkv<<<(N_NODES * 64 + 255) / 256, 256>>>(x, Wq1, bq1, Wk1, bk1, Wv1, bv1, Ws1, bs1);
    k_init_pool<<<(N_GRAPHS * 128 + 255) / 256, 256>>>();

    // join
    cudaStreamWaitEvent(0, ev_join, 0);
    cudaStreamWaitEvent(0, ev_join2, 0);

    // layer 1 edges
    k_edge1<<<PAIR_NODE_BLOCKS, 256>>>();

    // layer 2
    k_l2_qkv<<<dim3(N_NODES / 16, 2), 256>>>(Wq2, bq2, Wk2, bk2, Wv2, bv2, Ws2, bs2);
    k_edge2<<<PAIR_NODE_BLOCKS, 256>>>();
    k_pool<<<N_NODES / 32, 128>>>(batch);

    // head
    k_mlp<<<1, 256>>>(W1, b1, W2, b2, W3, b3, out);

    // re-zero metadata for the next call (off the critical path)
    k_zero_meta<<<(N_NODES + 255) / 256, 256>>>();
}

// round 16
// speedup vs baseline: 1.1194x; 1.1194x over previous
#include <cuda_runtime.h>
#include <cuda_fp16.h>
#include <math_constants.h>

#define N_NODES 100000
#define N_EDGES 1600000
#define N_GRAPHS 64
#define EPSV 1e-16f

// ---------------- scratch (device globals; no allocations) ----------------
__device__ float  g_q1[N_NODES * 64];
__device__ __half g_kv1h[N_NODES * 128];   // interleaved: [4k|4v] per 8-half group
__device__ float  g_s1[N_NODES * 64];
__device__ float  g_h1[N_NODES * 64];

__device__ float  g_q2[N_NODES * 128];     // after layer-2 edge pass, holds h2
__device__ __align__(32) __half g_kv2h[N_NODES * 256];   // interleaved: [8k|8v]
__device__ float  g_s2[N_NODES * 128];

__device__ float g_pool[N_GRAPHS * 128];

// CSR
__device__ int g_deg[N_NODES];
__device__ int g_rowptr[N_NODES + 1];
__device__ int g_cursor[N_NODES];
__device__ int g_esrc[N_EDGES];

// ---------------- helpers ----------------
__device__ __forceinline__ void atomicMaxF(float* addr, float val) {
    if (val >= 0.0f)
        atomicMax((int*)addr, __float_as_int(val));
    else
        atomicMin((unsigned int*)addr, __float_as_uint(val));
}

__device__ __forceinline__ unsigned long long pack_f2(float a, float b) {
    unsigned long long r;
    asm("mov.b64 %0, {%1, %2};" : "=l"(r) : "f"(a), "f"(b));
    return r;
}
__device__ __forceinline__ void ffma2(unsigned long long& d,
                                      unsigned long long a, unsigned long long b) {
    asm("fma.rn.f32x2 %0, %1, %2, %0;" : "+l"(d) : "l"(a), "l"(b));
}
__device__ __forceinline__ void unpack_f2(unsigned long long d, float& x, float& y) {
    asm("mov.b64 {%0, %1}, %2;" : "=f"(x), "=f"(y) : "l"(d));
}

// 256-bit global load (sm_100+)
__device__ __forceinline__ void ldg_v8(const void* p, uint4& a, uint4& b) {
    asm("ld.global.nc.v8.b32 {%0,%1,%2,%3,%4,%5,%6,%7}, [%8];"
        : "=r"(a.x), "=r"(a.y), "=r"(a.z), "=r"(a.w),
          "=r"(b.x), "=r"(b.y), "=r"(b.z), "=r"(b.w)
        : "l"(p));
}

// decode one uint4 (8 halves) -> two float4
__device__ __forceinline__ void dec_h8(uint4 u, float4& lo, float4& hi) {
    float2 a = __half22float2(*reinterpret_cast<const __half2*>(&u.x));
    float2 b = __half22float2(*reinterpret_cast<const __half2*>(&u.y));
    float2 c = __half22float2(*reinterpret_cast<const __half2*>(&u.z));
    float2 d = __half22float2(*reinterpret_cast<const __half2*>(&u.w));
    lo = make_float4(a.x, a.y, b.x, b.y);
    hi = make_float4(c.x, c.y, d.x, d.y);
}
__device__ __forceinline__ void dec_kv(uint4 u, float4& kk, float4& vv) {
    dec_h8(u, kk, vv);
}

// ================= CSR build =================
__global__ void k_zero_deg() {
    int i = blockIdx.x * blockDim.x + threadIdx.x;
    if (i < N_NODES) g_deg[i] = 0;
}

__global__ void k_hist(const int* __restrict__ ei) {
    int t = blockIdx.x * blockDim.x + threadIdx.x;
    if (t >= N_EDGES / 4) return;
    int4 d4 = __ldg((const int4*)(ei + N_EDGES) + t);
    atomicAdd(&g_deg[d4.x], 1);
    atomicAdd(&g_deg[d4.y], 1);
    atomicAdd(&g_deg[d4.z], 1);
    atomicAdd(&g_deg[d4.w], 1);
}

__global__ void k_scan() {
    __shared__ int s_sums[1024];
    const int CH = 98;
    int t = threadIdx.x;
    int base = t * CH;
    int sum = 0;
    for (int i = 0; i < CH; i++) {
        int idx = base + i;
        if (idx < N_NODES) sum += g_deg[idx];
    }
    s_sums[t] = sum;
    __syncthreads();
    for (int d = 1; d < 1024; d <<= 1) {
        int v = (t >= d) ? s_sums[t - d] : 0;
        __syncthreads();
        s_sums[t] += v;
        __syncthreads();
    }
    int run = s_sums[t] - sum;
    for (int i = 0; i < CH; i++) {
        int idx = base + i;
        if (idx < N_NODES) {
            g_rowptr[idx] = run;
            g_cursor[idx] = run;
            run += g_deg[idx];
        }
    }
    if (t == 1023) g_rowptr[N_NODES] = N_EDGES;
}

__global__ void k_scatter(const int* __restrict__ ei) {
    int t = blockIdx.x * blockDim.x + threadIdx.x;
    if (t >= N_EDGES / 4) return;
    int4 s4 = __ldg((const int4*)ei + t);
    int4 d4 = __ldg((const int4*)(ei + N_EDGES) + t);
    g_esrc[atomicAdd(&g_cursor[d4.x], 1)] = s4.x;
    g_esrc[atomicAdd(&g_cursor[d4.y], 1)] = s4.y;
    g_esrc[atomicAdd(&g_cursor[d4.z], 1)] = s4.z;
    g_esrc[atomicAdd(&g_cursor[d4.w], 1)] = s4.w;
}

// ---------------- layer 1: node QKV + skip ----------------
__global__ void k_l1_qkv(const float* __restrict__ x,
                         const float* __restrict__ Wq, const float* __restrict__ bq,
                         const float* __restrict__ Wk, const float* __restrict__ bk,
                         const float* __restrict__ Wv, const float* __restrict__ bv,
                         const float* __restrict__ Ws, const float* __restrict__ bs) {
    int idx = blockIdx.x * blockDim.x + threadIdx.x;
    if (idx >= N_NODES * 64) return;
    int n = idx >> 6;
    int j = idx & 63;
    float x0 = __ldg(x + n * 3 + 0);
    float x1 = __ldg(x + n * 3 + 1);
    float x2 = __ldg(x + n * 3 + 2);

    float q = __ldg(bq + j) + x0 * __ldg(Wq + j) + x1 * __ldg(Wq + 64 + j) + x2 * __ldg(Wq + 128 + j);
    float k = __ldg(bk + j) + x0 * __ldg(Wk + j) + x1 * __ldg(Wk + 64 + j) + x2 * __ldg(Wk + 128 + j);
    float v = __ldg(bv + j) + x0 * __ldg(Wv + j) + x1 * __ldg(Wv + 64 + j) + x2 * __ldg(Wv + 128 + j);
    float s = __ldg(bs + j) + x0 * __ldg(Ws + j) + x1 * __ldg(Ws + 64 + j) + x2 * __ldg(Ws + 128 + j);

    g_q1[idx] = q;
    int c = j >> 2, r = j & 3;
    g_kv1h[(size_t)n * 128 + c * 8 + r]     = __float2half(k);
    g_kv1h[(size_t)n * 128 + c * 8 + 4 + r] = __float2half(v);
    g_s1[idx] = s;
}

// ================= layer-1 fused edge pass: 2 nodes per warp ===============
__global__ void k_edge1() {
    const float RSC = 0.17677669529663687f;  // 1/sqrt(32)
    int gw = (blockIdx.x * blockDim.x + threadIdx.x) >> 5;
    int lane = threadIdx.x & 31;
    int half = lane >> 4;
    int hl = lane & 15;
    int n = gw * 2 + half;
    if (n >= N_NODES) return;                // N_NODES even -> warp uniform
    unsigned mask = half ? 0xFFFF0000u : 0x0000FFFFu;

    int beg = __ldg(&g_rowptr[n]);
    int end = __ldg(&g_rowptr[n + 1]);

    const uint4* kvb = (const uint4*)g_kv1h;  // 16 uint4 per row
    float4 qa = *(const float4*)(g_q1 + (size_t)n * 64 + hl * 4);
    float4 acc = make_float4(0.f, 0.f, 0.f, 0.f);
    float ssum = 0.0f;

    int idx = beg;
    for (; idx + 2 <= end; idx += 2) {
        int s0 = __ldg(&g_esrc[idx]);
        int s1 = __ldg(&g_esrc[idx + 1]);
        uint4 u0 = __ldg(kvb + (size_t)s0 * 16 + hl);
        uint4 u1 = __ldg(kvb + (size_t)s1 * 16 + hl);
        float4 k0, v0, k1, v1;
        dec_kv(u0, k0, v0);
        dec_kv(u1, k1, v1);
        float p0 = qa.x * k0.x + qa.y * k0.y + qa.z * k0.z + qa.w * k0.w;
        float p1 = qa.x * k1.x + qa.y * k1.y + qa.z * k1.z + qa.w * k1.w;
#pragma unroll
        for (int d = 4; d >= 1; d >>= 1) {
            p0 += __shfl_xor_sync(mask, p0, d);
            p1 += __shfl_xor_sync(mask, p1, d);
        }
        float e0 = __expf(p0 * RSC);
        float e1 = __expf(p1 * RSC);
        ssum += e0 + e1;
        acc.x += e0 * v0.x + e1 * v1.x;
        acc.y += e0 * v0.y + e1 * v1.y;
        acc.z += e0 * v0.z + e1 * v1.z;
        acc.w += e0 * v0.w + e1 * v1.w;
    }
    for (; idx < end; idx++) {
        int s0 = __ldg(&g_esrc[idx]);
        uint4 u0 = __ldg(kvb + (size_t)s0 * 16 + hl);
        float4 k0, v0;
        dec_kv(u0, k0, v0);
        float p0 = qa.x * k0.x + qa.y * k0.y + qa.z * k0.z + qa.w * k0.w;
#pragma unroll
        for (int d = 4; d >= 1; d >>= 1) p0 += __shfl_xor_sync(mask, p0, d);
        float e0 = __expf(p0 * RSC);
        ssum += e0;
        acc.x += e0 * v0.x; acc.y += e0 * v0.y;
        acc.z += e0 * v0.z; acc.w += e0 * v0.w;
    }
    float rh = 1.0f / (ssum + EPSV);
    float4 sk = *(const float4*)(g_s1 + (size_t)n * 64 + hl * 4);
    float4 o;
    o.x = fmaxf(acc.x * rh + sk.x, 0.0f);
    o.y = fmaxf(acc.y * rh + sk.y, 0.0f);
    o.z = fmaxf(acc.z * rh + sk.z, 0.0f);
    o.w = fmaxf(acc.w * rh + sk.w, 0.0f);
    *(float4*)(g_h1 + (size_t)n * 64 + hl * 4) = o;
}

// ================= layer-2 fused edge pass: 2 nodes per warp ===============
__global__ void k_edge2() {
    const float RSC = 0.125f;  // 1/sqrt(64)
    int gw = (blockIdx.x * blockDim.x + threadIdx.x) >> 5;
    int lane = threadIdx.x & 31;
    int half = lane >> 4;
    int hl = lane & 15;
    int n = gw * 2 + half;
    if (n >= N_NODES) return;
    unsigned mask = half ? 0xFFFF0000u : 0x0000FFFFu;

    int beg = __ldg(&g_rowptr[n]);
    int end = __ldg(&g_rowptr[n + 1]);

    const uint4* kvb = (const uint4*)g_kv2h;  // 32 uint4 per row
    float4 qa = *(const float4*)(g_q2 + (size_t)n * 128 + hl * 8);
    float4 qb = *(const float4*)(g_q2 + (size_t)n * 128 + hl * 8 + 4);
    float4 accA = make_float4(0.f, 0.f, 0.f, 0.f);
    float4 accB = make_float4(0.f, 0.f, 0.f, 0.f);
    float ssum = 0.0f;

    int idx = beg;
    for (; idx + 2 <= end; idx += 2) {
        int s0 = __ldg(&g_esrc[idx]);
        int s1 = __ldg(&g_esrc[idx + 1]);
        uint4 uk0, uv0, uk1, uv1;
        ldg_v8(kvb + (size_t)s0 * 32 + hl * 2, uk0, uv0);
        ldg_v8(kvb + (size_t)s1 * 32 + hl * 2, uk1, uv1);
        float4 k0a, k0b, k1a, k1b;
        dec_h8(uk0, k0a, k0b);
        dec_h8(uk1, k1a, k1b);
        float p0 = qa.x * k0a.x + qa.y * k0a.y + qa.z * k0a.z + qa.w * k0a.w
                 + qb.x * k0b.x + qb.y * k0b.y + qb.z * k0b.z + qb.w * k0b.w;
        float p1 = qa.x * k1a.x + qa.y * k1a.y + qa.z * k1a.z + qa.w * k1a.w
                 + qb.x * k1b.x + qb.y * k1b.y + qb.z * k1b.z + qb.w * k1b.w;
#pragma unroll
        for (int d = 4; d >= 1; d >>= 1) {
            p0 += __shfl_xor_sync(mask, p0, d);
            p1 += __shfl_xor_sync(mask, p1, d);
        }
        float e0 = __expf(p0 * RSC);
        float e1 = __expf(p1 * RSC);
        ssum += e0 + e1;
        float4 v0a, v0b, v1a, v1b;
        dec_h8(uv0, v0a, v0b);
        dec_h8(uv1, v1a, v1b);
        accA.x += e0 * v0a.x + e1 * v1a.x;
        accA.y += e0 * v0a.y + e1 * v1a.y;
        accA.z += e0 * v0a.z + e1 * v1a.z;
        accA.w += e0 * v0a.w + e1 * v1a.w;
        accB.x += e0 * v0b.x + e1 * v1b.x;
        accB.y += e0 * v0b.y + e1 * v1b.y;
        accB.z += e0 * v0b.z + e1 * v1b.z;
        accB.w += e0 * v0b.w + e1 * v1b.w;
    }
    for (; idx < end; idx++) {
        int s0 = __ldg(&g_esrc[idx]);
        uint4 uk0, uv0;
        ldg_v8(kvb + (size_t)s0 * 32 + hl * 2, uk0, uv0);
        float4 k0a, k0b;
        dec_h8(uk0, k0a, k0b);
        float p0 = qa.x * k0a.x + qa.y * k0a.y + qa.z * k0a.z + qa.w * k0a.w
                 + qb.x * k0b.x + qb.y * k0b.y + qb.z * k0b.z + qb.w * k0b.w;
#pragma unroll
        for (int d = 4; d >= 1; d >>= 1) p0 += __shfl_xor_sync(mask, p0, d);
        float e0 = __expf(p0 * RSC);
        ssum += e0;
        float4 v0a, v0b;
        dec_h8(uv0, v0a, v0b);
        accA.x += e0 * v0a.x; accA.y += e0 * v0a.y;
        accA.z += e0 * v0a.z; accA.w += e0 * v0a.w;
        accB.x += e0 * v0b.x; accB.y += e0 * v0b.y;
        accB.z += e0 * v0b.z; accB.w += e0 * v0b.w;
    }
    float rh = 1.0f / (ssum + EPSV);
    float4 skA = *(const float4*)(g_s2 + (size_t)n * 128 + hl * 8);
    float4 skB = *(const float4*)(g_s2 + (size_t)n * 128 + hl * 8 + 4);
    float4 oA, oB;
    oA.x = fmaxf(accA.x * rh + skA.x, 0.0f);
    oA.y = fmaxf(accA.y * rh + skA.y, 0.0f);
    oA.z = fmaxf(accA.z * rh + skA.z, 0.0f);
    oA.w = fmaxf(accA.w * rh + skA.w, 0.0f);
    oB.x = fmaxf(accB.x * rh + skB.x, 0.0f);
    oB.y = fmaxf(accB.y * rh + skB.y, 0.0f);
    oB.z = fmaxf(accB.z * rh + skB.z, 0.0f);
    oB.w = fmaxf(accB.w * rh + skB.w, 0.0f);
    *(float4*)(g_q2 + (size_t)n * 128 + hl * 8) = oA;      // h2 in place
    *(float4*)(g_q2 + (size_t)n * 128 + hl * 8 + 4) = oB;
}

// ---------------- layer 2 GEMM: f32x2 packed, smem-staged h1 ----------------
__global__ void k_l2_qkv(const float* __restrict__ Wq, const float* __restrict__ bq,
                         const float* __restrict__ Wk, const float* __restrict__ bk,
                         const float* __restrict__ Wv, const float* __restrict__ bv,
                         const float* __restrict__ Ws, const float* __restrict__ bs) {
    __shared__ __align__(16) float shT[64][20];
    int tid = threadIdx.x;
    int nb = blockIdx.x * 16;

    {
        float4 f = *(const float4*)(g_h1 + (size_t)nb * 64 + tid * 4);
        int node = tid >> 4;
        int i0 = (tid & 15) * 4;
        shT[i0 + 0][node] = f.x;
        shT[i0 + 1][node] = f.y;
        shT[i0 + 2][node] = f.z;
        shT[i0 + 3][node] = f.w;
    }
    __syncthreads();

    int mat = blockIdx.y * 2 + (tid >> 7);   // 0..3
    int j = tid & 127;
    const float* W; const float* B;
    if (mat == 0)      { W = Wq; B = bq; }
    else if (mat == 1) { W = Wk; B = bk; }
    else if (mat == 2) { W = Wv; B = bv; }
    else               { W = Ws; B = bs; }

    float bj = __ldg(B + j);
    unsigned long long acc[8];
#pragma unroll
    for (int r = 0; r < 8; r++) acc[r] = pack_f2(bj, bj);

    const unsigned long long* shT64 = (const unsigned long long*)&shT[0][0];
    for (int i = 0; i < 64; i++) {
        float w = __ldg(W + i * 128 + j);
        unsigned long long wp = pack_f2(w, w);
        int rb = i * 10;                     // 20 floats = 10 ull per row
#pragma unroll
        for (int r4 = 0; r4 < 4; r4++) {
            unsigned long long hp0 = shT64[rb + r4 * 2 + 0];
            unsigned long long hp1 = shT64[rb + r4 * 2 + 1];
            ffma2(acc[2 * r4 + 0], hp0, wp);
            ffma2(acc[2 * r4 + 1], hp1, wp);
        }
    }
    if (mat == 0 || mat == 3) {
        float* Of = (mat == 0) ? g_q2 : g_s2;
#pragma unroll
        for (int r = 0; r < 8; r++) {
            float o0, o1;
            unpack_f2(acc[r], o0, o1);
            Of[(size_t)(nb + 2 * r + 0) * 128 + j] = o0;
            Of[(size_t)(nb + 2 * r + 1) * 128 + j] = o1;
        }
    } else {
        // interleaved kv2 [8k|8v]: k col j -> (j>>3)*16 + (j&7); v -> +8
        int jj = ((j >> 3) * 16) + (j & 7) + ((mat == 2) ? 8 : 0);
#pragma unroll
        for (int r = 0; r < 8; r++) {
            float o0, o1;
            unpack_f2(acc[r], o0, o1);
            g_kv2h[(size_t)(nb + 2 * r + 0) * 256 + jj] = __float2half(o0);
            g_kv2h[(size_t)(nb + 2 * r + 1) * 256 + jj] = __float2half(o1);
        }
    }
}

// ---------------- pool init ----------------
__global__ void k_init_pool() {
    int i = blockIdx.x * blockDim.x + threadIdx.x;
    if (i < N_GRAPHS * 128) g_pool[i] = -CUDART_INF_F;
}

// ---------------- pool: run-length max over sorted batch (32 nodes/block) --
__global__ void k_pool(const int* __restrict__ batch) {
    int j = threadIdx.x;
    int n0 = blockIdx.x * 32;
    float cur = -CUDART_INF_F;
    int curg = __ldg(batch + n0);
#pragma unroll 4
    for (int r = 0; r < 32; r++) {
        int n = n0 + r;
        int g = __ldg(batch + n);
        if (g != curg) {
            atomicMaxF(&g_pool[curg * 128 + j], cur);
            cur = -CUDART_INF_F;
            curg = g;
        }
        cur = fmaxf(cur, g_q2[(size_t)n * 128 + j]);   // h2 lives in g_q2
    }
    atomicMaxF(&g_pool[curg * 128 + j], cur);
}

// ---------------- MLP head: one block per graph ----------------
__global__ void k_mlp(const float* __restrict__ W1, const float* __restrict__ b1,
                      const float* __restrict__ W2, const float* __restrict__ b2,
                      const float* __restrict__ W3, const float* __restrict__ b3,
                      float* __restrict__ out) {
    __shared__ float s_pool[128];
    __shared__ float s_lat[32];
    __shared__ float s_h[128];
    int g = blockIdx.x;                 // 0..63
    int tid = threadIdx.x;              // 0..127

    s_pool[tid] = g_pool[g * 128 + tid];
    __syncthreads();

    // latent = relu(pool @ W1 + b1)  [32]
    if (tid < 32) {
        float a = __ldg(b1 + tid);
        for (int i = 0; i < 128; i++) a += s_pool[i] * __ldg(W1 + i * 32 + tid);
        a = fmaxf(a, 0.0f);
        s_lat[tid] = a;
        out[2560 + g * 32 + tid] = a;   // latent second in output
    }
    __syncthreads();

    // h2 = relu(latent @ W2 + b2)  [128]
    {
        float a = __ldg(b2 + tid);
        for (int i = 0; i < 32; i++) a += s_lat[i] * __ldg(W2 + i * 128 + tid);
        s_h[tid] = fmaxf(a, 0.0f);
    }
    __syncthreads();

    // logits = h2 @ W3 + b3  [40]
    if (tid < 40) {
        float a = __ldg(b3 + tid);
        for (int i = 0; i < 128; i++) a += s_h[i] * __ldg(W3 + i * 40 + tid);
        out[g * 40 + tid] = a;          // logits first in output
    }
}

// ---------------- launch ----------------
extern "C" void kernel_launch(void* const* d_in, const int* in_sizes, int n_in,
                              void* d_out, int out_size) {
    const float* x     = (const float*)d_in[0];
    const int*   ei    = (const int*)d_in[1];
    const int*   batch = (const int*)d_in[2];
    const float *Wq1 = (const float*)d_in[3],  *bq1 = (const float*)d_in[4];
    const float *Wk1 = (const float*)d_in[5],  *bk1 = (const float*)d_in[6];
    const float *Wv1 = (const float*)d_in[7],  *bv1 = (const float*)d_in[8];
    const float *Ws1 = (const float*)d_in[9],  *bs1 = (const float*)d_in[10];
    const float *Wq2 = (const float*)d_in[11], *bq2 = (const float*)d_in[12];
    const float *Wk2 = (const float*)d_in[13], *bk2 = (const float*)d_in[14];
    const float *Wv2 = (const float*)d_in[15], *bv2 = (const float*)d_in[16];
    const float *Ws2 = (const float*)d_in[17], *bs2 = (const float*)d_in[18];
    const float *W1  = (const float*)d_in[19], *b1  = (const float*)d_in[20];
    const float *W2  = (const float*)d_in[21], *b2  = (const float*)d_in[22];
    const float *W3  = (const float*)d_in[23], *b3  = (const float*)d_in[24];
    float* out = (float*)d_out;

    // one-time side stream + fork/join events (host-side resources only)
    static cudaStream_t s_side = nullptr;
    static cudaEvent_t ev_fork = nullptr, ev_join = nullptr;
    if (s_side == nullptr) {
        cudaStreamCreateWithFlags(&s_side, cudaStreamNonBlocking);
        cudaEventCreateWithFlags(&ev_fork, cudaEventDisableTiming);
        cudaEventCreateWithFlags(&ev_join, cudaEventDisableTiming);
    }

    const int PAIR_NODE_BLOCKS = ((N_NODES / 2) * 32 + 255) / 256;  // 2 nodes/warp

    // fork: CSR build on side stream (g_deg zeroed at tail of previous call;
    // device globals start zeroed on module load for the first call)
    cudaEventRecord(ev_fork, 0);
    cudaStreamWaitEvent(s_side, ev_fork, 0);
    k_hist<<<(N_EDGES / 4 + 255) / 256, 256, 0, s_side>>>(ei);
    k_scan<<<1, 1024, 0, s_side>>>();
    k_scatter<<<(N_EDGES / 4 + 255) / 256, 256, 0, s_side>>>(ei);
    cudaEventRecord(ev_join, s_side);

    // main stream: node-parallel work that doesn't need the CSR
    k_l1_qkv<<<(N_NODES * 64 + 255) / 256, 256>>>(x, Wq1, bq1, Wk1, bk1, Wv1, bv1, Ws1, bs1);
    k_init_pool<<<(N_GRAPHS * 128 + 255) / 256, 256>>>();

    // join
    cudaStreamWaitEvent(0, ev_join, 0);

    // layer 1 edges
    k_edge1<<<PAIR_NODE_BLOCKS, 256>>>();

    // layer 2
    k_l2_qkv<<<dim3(N_NODES / 16, 2), 256>>>(Wq2, bq2, Wk2, bk2, Wv2, bv2, Ws2, bs2);
    k_edge2<<<PAIR_NODE_BLOCKS, 256>>>();
    k_pool<<<N_NODES / 32, 128>>>(batch);

    // head: one block per graph
    k_mlp<<<N_GRAPHS, 128>>>(W1, b1, W2, b2, W3, b3, out);

    // re-zero degree array for the next call (off the critical path)
    k_zero_deg<<<(N_NODES + 255) / 256, 256>>>();
}

// round 17
// speedup vs baseline: 1.3796x; 1.2324x over previous
#include <cuda_runtime.h>
#include <cuda_fp16.h>
#include <math_constants.h>

#define N_NODES 100000
#define N_EDGES 1600000
#define N_GRAPHS 64
#define EPSV 1e-16f

// ---------------- scratch (device globals; no allocations) ----------------
__device__ float  g_q1[N_NODES * 64];
__device__ __half g_kv1h[N_NODES * 128];   // interleaved: [4k|4v] per 8-half group
__device__ float  g_s1[N_NODES * 64];
__device__ __half g_h1h[N_NODES * 64];     // h1 in fp16 (feeds tensor-core GEMM)

__device__ float  g_q2[N_NODES * 128];     // after layer-2 edge pass, holds h2
__device__ __align__(32) __half g_kv2h[N_NODES * 256];   // interleaved: [8k|8v]
__device__ float  g_s2[N_NODES * 128];

__device__ float g_pool[N_GRAPHS * 128];

// CSR
__device__ int g_deg[N_NODES];
__device__ int g_rowptr[N_NODES + 1];
__device__ int g_cursor[N_NODES];
__device__ int g_esrc[N_EDGES];

// ---------------- helpers ----------------
__device__ __forceinline__ void atomicMaxF(float* addr, float val) {
    if (val >= 0.0f)
        atomicMax((int*)addr, __float_as_int(val));
    else
        atomicMin((unsigned int*)addr, __float_as_uint(val));
}

// 256-bit global load (sm_100+)
__device__ __forceinline__ void ldg_v8(const void* p, uint4& a, uint4& b) {
    asm("ld.global.nc.v8.b32 {%0,%1,%2,%3,%4,%5,%6,%7}, [%8];"
        : "=r"(a.x), "=r"(a.y), "=r"(a.z), "=r"(a.w),
          "=r"(b.x), "=r"(b.y), "=r"(b.z), "=r"(b.w)
        : "l"(p));
}

// decode one uint4 (8 halves) -> two float4
__device__ __forceinline__ void dec_h8(uint4 u, float4& lo, float4& hi) {
    float2 a = __half22float2(*reinterpret_cast<const __half2*>(&u.x));
    float2 b = __half22float2(*reinterpret_cast<const __half2*>(&u.y));
    float2 c = __half22float2(*reinterpret_cast<const __half2*>(&u.z));
    float2 d = __half22float2(*reinterpret_cast<const __half2*>(&u.w));
    lo = make_float4(a.x, a.y, b.x, b.y);
    hi = make_float4(c.x, c.y, d.x, d.y);
}
__device__ __forceinline__ void dec_kv(uint4 u, float4& kk, float4& vv) {
    dec_h8(u, kk, vv);
}

__device__ __forceinline__ void mma16816(float& c0, float& c1, float& c2, float& c3,
                                         unsigned a0, unsigned a1, unsigned a2, unsigned a3,
                                         unsigned b0, unsigned b1) {
    asm volatile(
        "mma.sync.aligned.m16n8k16.row.col.f32.f16.f16.f32 "
        "{%0,%1,%2,%3}, {%4,%5,%6,%7}, {%8,%9}, {%0,%1,%2,%3};"
        : "+f"(c0), "+f"(c1), "+f"(c2), "+f"(c3)
        : "r"(a0), "r"(a1), "r"(a2), "r"(a3), "r"(b0), "r"(b1));
}

// ================= CSR build =================
__global__ void k_zero_deg() {
    int i = blockIdx.x * blockDim.x + threadIdx.x;
    if (i < N_NODES) g_deg[i] = 0;
}

__global__ void k_hist(const int* __restrict__ ei) {
    int t = blockIdx.x * blockDim.x + threadIdx.x;
    if (t >= N_EDGES / 4) return;
    int4 d4 = __ldg((const int4*)(ei + N_EDGES) + t);
    atomicAdd(&g_deg[d4.x], 1);
    atomicAdd(&g_deg[d4.y], 1);
    atomicAdd(&g_deg[d4.z], 1);
    atomicAdd(&g_deg[d4.w], 1);
}

__global__ void k_scan() {
    __shared__ int s_sums[1024];
    const int CH = 98;
    int t = threadIdx.x;
    int base = t * CH;
    int sum = 0;
    for (int i = 0; i < CH; i++) {
        int idx = base + i;
        if (idx < N_NODES) sum += g_deg[idx];
    }
    s_sums[t] = sum;
    __syncthreads();
    for (int d = 1; d < 1024; d <<= 1) {
        int v = (t >= d) ? s_sums[t - d] : 0;
        __syncthreads();
        s_sums[t] += v;
        __syncthreads();
    }
    int run = s_sums[t] - sum;
    for (int i = 0; i < CH; i++) {
        int idx = base + i;
        if (idx < N_NODES) {
            g_rowptr[idx] = run;
            g_cursor[idx] = run;
            run += g_deg[idx];
        }
    }
    if (t == 1023) g_rowptr[N_NODES] = N_EDGES;
}

__global__ void k_scatter(const int* __restrict__ ei) {
    int t = blockIdx.x * blockDim.x + threadIdx.x;
    if (t >= N_EDGES / 4) return;
    int4 s4 = __ldg((const int4*)ei + t);
    int4 d4 = __ldg((const int4*)(ei + N_EDGES) + t);
    g_esrc[atomicAdd(&g_cursor[d4.x], 1)] = s4.x;
    g_esrc[atomicAdd(&g_cursor[d4.y], 1)] = s4.y;
    g_esrc[atomicAdd(&g_cursor[d4.z], 1)] = s4.z;
    g_esrc[atomicAdd(&g_cursor[d4.w], 1)] = s4.w;
}

// ---------------- layer 1: node QKV + skip ----------------
__global__ void k_l1_qkv(const float* __restrict__ x,
                         const float* __restrict__ Wq, const float* __restrict__ bq,
                         const float* __restrict__ Wk, const float* __restrict__ bk,
                         const float* __restrict__ Wv, const float* __restrict__ bv,
                         const float* __restrict__ Ws, const float* __restrict__ bs) {
    int idx = blockIdx.x * blockDim.x + threadIdx.x;
    if (idx >= N_NODES * 64) return;
    int n = idx >> 6;
    int j = idx & 63;
    float x0 = __ldg(x + n * 3 + 0);
    float x1 = __ldg(x + n * 3 + 1);
    float x2 = __ldg(x + n * 3 + 2);

    float q = __ldg(bq + j) + x0 * __ldg(Wq + j) + x1 * __ldg(Wq + 64 + j) + x2 * __ldg(Wq + 128 + j);
    float k = __ldg(bk + j) + x0 * __ldg(Wk + j) + x1 * __ldg(Wk + 64 + j) + x2 * __ldg(Wk + 128 + j);
    float v = __ldg(bv + j) + x0 * __ldg(Wv + j) + x1 * __ldg(Wv + 64 + j) + x2 * __ldg(Wv + 128 + j);
    float s = __ldg(bs + j) + x0 * __ldg(Ws + j) + x1 * __ldg(Ws + 64 + j) + x2 * __ldg(Ws + 128 + j);

    g_q1[idx] = q;
    int c = j >> 2, r = j & 3;
    g_kv1h[(size_t)n * 128 + c * 8 + r]     = __float2half(k);
    g_kv1h[(size_t)n * 128 + c * 8 + 4 + r] = __float2half(v);
    g_s1[idx] = s;
}

// ================= layer-1 fused edge pass: 2 nodes per warp ===============
__global__ void k_edge1() {
    const float RSC = 0.17677669529663687f;  // 1/sqrt(32)
    int gw = (blockIdx.x * blockDim.x + threadIdx.x) >> 5;
    int lane = threadIdx.x & 31;
    int half = lane >> 4;
    int hl = lane & 15;
    int n = gw * 2 + half;
    if (n >= N_NODES) return;                // N_NODES even -> warp uniform
    unsigned mask = half ? 0xFFFF0000u : 0x0000FFFFu;

    int beg = __ldg(&g_rowptr[n]);
    int end = __ldg(&g_rowptr[n + 1]);

    const uint4* kvb = (const uint4*)g_kv1h;  // 16 uint4 per row
    float4 qa = *(const float4*)(g_q1 + (size_t)n * 64 + hl * 4);
    float4 acc = make_float4(0.f, 0.f, 0.f, 0.f);
    float ssum = 0.0f;

    int idx = beg;
    for (; idx + 2 <= end; idx += 2) {
        int s0 = __ldg(&g_esrc[idx]);
        int s1 = __ldg(&g_esrc[idx + 1]);
        uint4 u0 = __ldg(kvb + (size_t)s0 * 16 + hl);
        uint4 u1 = __ldg(kvb + (size_t)s1 * 16 + hl);
        float4 k0, v0, k1, v1;
        dec_kv(u0, k0, v0);
        dec_kv(u1, k1, v1);
        float p0 = qa.x * k0.x + qa.y * k0.y + qa.z * k0.z + qa.w * k0.w;
        float p1 = qa.x * k1.x + qa.y * k1.y + qa.z * k1.z + qa.w * k1.w;
#pragma unroll
        for (int d = 4; d >= 1; d >>= 1) {
            p0 += __shfl_xor_sync(mask, p0, d);
            p1 += __shfl_xor_sync(mask, p1, d);
        }
        float e0 = __expf(p0 * RSC);
        float e1 = __expf(p1 * RSC);
        ssum += e0 + e1;
        acc.x += e0 * v0.x + e1 * v1.x;
        acc.y += e0 * v0.y + e1 * v1.y;
        acc.z += e0 * v0.z + e1 * v1.z;
        acc.w += e0 * v0.w + e1 * v1.w;
    }
    for (; idx < end; idx++) {
        int s0 = __ldg(&g_esrc[idx]);
        uint4 u0 = __ldg(kvb + (size_t)s0 * 16 + hl);
        float4 k0, v0;
        dec_kv(u0, k0, v0);
        float p0 = qa.x * k0.x + qa.y * k0.y + qa.z * k0.z + qa.w * k0.w;
#pragma unroll
        for (int d = 4; d >= 1; d >>= 1) p0 += __shfl_xor_sync(mask, p0, d);
        float e0 = __expf(p0 * RSC);
        ssum += e0;
        acc.x += e0 * v0.x; acc.y += e0 * v0.y;
        acc.z += e0 * v0.z; acc.w += e0 * v0.w;
    }
    float rh = 1.0f / (ssum + EPSV);
    float4 sk = *(const float4*)(g_s1 + (size_t)n * 64 + hl * 4);
    __half2 h01 = __floats2half2_rn(fmaxf(acc.x * rh + sk.x, 0.0f),
                                    fmaxf(acc.y * rh + sk.y, 0.0f));
    __half2 h23 = __floats2half2_rn(fmaxf(acc.z * rh + sk.z, 0.0f),
                                    fmaxf(acc.w * rh + sk.w, 0.0f));
    uint2 packed;
    packed.x = *reinterpret_cast<unsigned*>(&h01);
    packed.y = *reinterpret_cast<unsigned*>(&h23);
    *(uint2*)(g_h1h + (size_t)n * 64 + hl * 4) = packed;
}

// ================= layer-2 fused edge pass: 2 nodes per warp ===============
__global__ void k_edge2() {
    const float RSC = 0.125f;  // 1/sqrt(64)
    int gw = (blockIdx.x * blockDim.x + threadIdx.x) >> 5;
    int lane = threadIdx.x & 31;
    int half = lane >> 4;
    int hl = lane & 15;
    int n = gw * 2 + half;
    if (n >= N_NODES) return;
    unsigned mask = half ? 0xFFFF0000u : 0x0000FFFFu;

    int beg = __ldg(&g_rowptr[n]);
    int end = __ldg(&g_rowptr[n + 1]);

    const uint4* kvb = (const uint4*)g_kv2h;  // 32 uint4 per row
    float4 qa = *(const float4*)(g_q2 + (size_t)n * 128 + hl * 8);
    float4 qb = *(const float4*)(g_q2 + (size_t)n * 128 + hl * 8 + 4);
    float4 accA = make_float4(0.f, 0.f, 0.f, 0.f);
    float4 accB = make_float4(0.f, 0.f, 0.f, 0.f);
    float ssum = 0.0f;

    int idx = beg;
    for (; idx + 2 <= end; idx += 2) {
        int s0 = __ldg(&g_esrc[idx]);
        int s1 = __ldg(&g_esrc[idx + 1]);
        uint4 uk0, uv0, uk1, uv1;
        ldg_v8(kvb + (size_t)s0 * 32 + hl * 2, uk0, uv0);
        ldg_v8(kvb + (size_t)s1 * 32 + hl * 2, uk1, uv1);
        float4 k0a, k0b, k1a, k1b;
        dec_h8(uk0, k0a, k0b);
        dec_h8(uk1, k1a, k1b);
        float p0 = qa.x * k0a.x + qa.y * k0a.y + qa.z * k0a.z + qa.w * k0a.w
                 + qb.x * k0b.x + qb.y * k0b.y + qb.z * k0b.z + qb.w * k0b.w;
        float p1 = qa.x * k1a.x + qa.y * k1a.y + qa.z * k1a.z + qa.w * k1a.w
                 + qb.x * k1b.x + qb.y * k1b.y + qb.z * k1b.z + qb.w * k1b.w;
#pragma unroll
        for (int d = 4; d >= 1; d >>= 1) {
            p0 += __shfl_xor_sync(mask, p0, d);
            p1 += __shfl_xor_sync(mask, p1, d);
        }
        float e0 = __expf(p0 * RSC);
        float e1 = __expf(p1 * RSC);
        ssum += e0 + e1;
        float4 v0a, v0b, v1a, v1b;
        dec_h8(uv0, v0a, v0b);
        dec_h8(uv1, v1a, v1b);
        accA.x += e0 * v0a.x + e1 * v1a.x;
        accA.y += e0 * v0a.y + e1 * v1a.y;
        accA.z += e0 * v0a.z + e1 * v1a.z;
        accA.w += e0 * v0a.w + e1 * v1a.w;
        accB.x += e0 * v0b.x + e1 * v1b.x;
        accB.y += e0 * v0b.y + e1 * v1b.y;
        accB.z += e0 * v0b.z + e1 * v1b.z;
        accB.w += e0 * v0b.w + e1 * v1b.w;
    }
    for (; idx < end; idx++) {
        int s0 = __ldg(&g_esrc[idx]);
        uint4 uk0, uv0;
        ldg_v8(kvb + (size_t)s0 * 32 + hl * 2, uk0, uv0);
        float4 k0a, k0b;
        dec_h8(uk0, k0a, k0b);
        float p0 = qa.x * k0a.x + qa.y * k0a.y + qa.z * k0a.z + qa.w * k0a.w
                 + qb.x * k0b.x + qb.y * k0b.y + qb.z * k0b.z + qb.w * k0b.w;
#pragma unroll
        for (int d = 4; d >= 1; d >>= 1) p0 += __shfl_xor_sync(mask, p0, d);
        float e0 = __expf(p0 * RSC);
        ssum += e0;
        float4 v0a, v0b;
        dec_h8(uv0, v0a, v0b);
        accA.x += e0 * v0a.x; accA.y += e0 * v0a.y;
        accA.z += e0 * v0a.z; accA.w += e0 * v0a.w;
        accB.x += e0 * v0b.x; accB.y += e0 * v0b.y;
        accB.z += e0 * v0b.z; accB.w += e0 * v0b.w;
    }
    float rh = 1.0f / (ssum + EPSV);
    float4 skA = *(const float4*)(g_s2 + (size_t)n * 128 + hl * 8);
    float4 skB = *(const float4*)(g_s2 + (size_t)n * 128 + hl * 8 + 4);
    float4 oA, oB;
    oA.x = fmaxf(accA.x * rh + skA.x, 0.0f);
    oA.y = fmaxf(accA.y * rh + skA.y, 0.0f);
    oA.z = fmaxf(accA.z * rh + skA.z, 0.0f);
    oA.w = fmaxf(accA.w * rh + skA.w, 0.0f);
    oB.x = fmaxf(accB.x * rh + skB.x, 0.0f);
    oB.y = fmaxf(accB.y * rh + skB.y, 0.0f);
    oB.z = fmaxf(accB.z * rh + skB.z, 0.0f);
    oB.w = fmaxf(accB.w * rh + skB.w, 0.0f);
    *(float4*)(g_q2 + (size_t)n * 128 + hl * 8) = oA;      // h2 in place
    *(float4*)(g_q2 + (size_t)n * 128 + hl * 8 + 4) = oB;
}

// ---------- layer 2 GEMM: tensor-core mma.sync (fp16 in, fp32 accum) -------
// Block: 128 nodes x one matrix (grid.y 0..3). 8 warps, each 16 rows x 128 cols.
__global__ void k_l2_qkv(const float* __restrict__ Wq, const float* __restrict__ bq,
                         const float* __restrict__ Wk, const float* __restrict__ bk,
                         const float* __restrict__ Wv, const float* __restrict__ bv,
                         const float* __restrict__ Ws, const float* __restrict__ bs) {
    __shared__ __half sA[128][72];    // A tile: rows x K (padded stride 72)
    __shared__ __half sBT[128][72];   // B transposed: N x K
    __shared__ float sBias[128];
    int tid = threadIdx.x;
    int mat = blockIdx.y;
    const float* W; const float* B;
    if (mat == 0)      { W = Wq; B = bq; }
    else if (mat == 1) { W = Wk; B = bk; }
    else if (mat == 2) { W = Wv; B = bv; }
    else               { W = Ws; B = bs; }

    int nb = blockIdx.x * 128;

    // stage A (guard tail rows)
    for (int i = tid; i < 128 * 8; i += 256) {       // 8-half chunks
        int row = i >> 3, c8 = (i & 7) * 8;
        uint4 val = make_uint4(0u, 0u, 0u, 0u);
        if (nb + row < N_NODES)
            val = *(const uint4*)(g_h1h + (size_t)(nb + row) * 64 + c8);
        *(uint4*)&sA[row][c8] = val;
    }
    // stage B transposed + fp16 convert
    for (int i = tid; i < 64 * 128; i += 256) {
        int k = i >> 7, n = i & 127;
        sBT[n][k] = __float2half(__ldg(W + k * 128 + n));
    }
    if (tid < 128) sBias[tid] = __ldg(B + tid);
    __syncthreads();

    int warp = tid >> 5, lane = tid & 31;
    int gid = lane >> 2, tig = lane & 3;
    int mrow = warp * 16;

    float acc[16][4];
#pragma unroll
    for (int n = 0; n < 16; n++) {
        float bz0 = sBias[n * 8 + 2 * tig];
        float bz1 = sBias[n * 8 + 2 * tig + 1];
        acc[n][0] = bz0; acc[n][1] = bz1;
        acc[n][2] = bz0; acc[n][3] = bz1;
    }

#pragma unroll
    for (int kk = 0; kk < 64; kk += 16) {
        unsigned a0 = *(const unsigned*)&sA[mrow + gid][kk + 2 * tig];
        unsigned a1 = *(const unsigned*)&sA[mrow + gid + 8][kk + 2 * tig];
        unsigned a2 = *(const unsigned*)&sA[mrow + gid][kk + 2 * tig + 8];
        unsigned a3 = *(const unsigned*)&sA[mrow + gid + 8][kk + 2 * tig + 8];
#pragma unroll
        for (int n = 0; n < 16; n++) {
            unsigned b0 = *(const unsigned*)&sBT[n * 8 + gid][kk + 2 * tig];
            unsigned b1 = *(const unsigned*)&sBT[n * 8 + gid][kk + 2 * tig + 8];
            mma16816(acc[n][0], acc[n][1], acc[n][2], acc[n][3],
                     a0, a1, a2, a3, b0, b1);
        }
    }

    // epilogue
    int row0 = nb + mrow + gid;
    int row1 = row0 + 8;
    if (mat == 0 || mat == 3) {
        float* Of = (mat == 0) ? g_q2 : g_s2;
#pragma unroll
        for (int n = 0; n < 16; n++) {
            int col = n * 8 + 2 * tig;
            if (row0 < N_NODES)
                *(float2*)(Of + (size_t)row0 * 128 + col) = make_float2(acc[n][0], acc[n][1]);
            if (row1 < N_NODES)
                *(float2*)(Of + (size_t)row1 * 128 + col) = make_float2(acc[n][2], acc[n][3]);
        }
    } else {
        int voff = (mat == 2) ? 8 : 0;
#pragma unroll
        for (int n = 0; n < 16; n++) {
            int col = n * 8 + 2 * tig;                    // even, col&7 in {0,2,4,6}
            int jj = ((col >> 3) * 16) + (col & 7) + voff; // jj, jj+1 contiguous
            if (row0 < N_NODES) {
                __half2 h = __floats2half2_rn(acc[n][0], acc[n][1]);
                *(__half2*)(g_kv2h + (size_t)row0 * 256 + jj) = h;
            }
            if (row1 < N_NODES) {
                __half2 h = __floats2half2_rn(acc[n][2], acc[n][3]);
                *(__half2*)(g_kv2h + (size_t)row1 * 256 + jj) = h;
            }
        }
    }
}

// ---------------- pool init ----------------
__global__ void k_init_pool() {
    int i = blockIdx.x * blockDim.x + threadIdx.x;
    if (i < N_GRAPHS * 128) g_pool[i] = -CUDART_INF_F;
}

// ---------------- pool: run-length max over sorted batch (32 nodes/block) --
__global__ void k_pool(const int* __restrict__ batch) {
    int j = threadIdx.x;
    int n0 = blockIdx.x * 32;
    float cur = -CUDART_INF_F;
    int curg = __ldg(batch + n0);
#pragma unroll 4
    for (int r = 0; r < 32; r++) {
        int n = n0 + r;
        int g = __ldg(batch + n);
        if (g != curg) {
            atomicMaxF(&g_pool[curg * 128 + j], cur);
            cur = -CUDART_INF_F;
            curg = g;
        }
        cur = fmaxf(cur, g_q2[(size_t)n * 128 + j]);   // h2 lives in g_q2
    }
    atomicMaxF(&g_pool[curg * 128 + j], cur);
}

// ---------------- MLP head: one block per graph ----------------
__global__ void k_mlp(const float* __restrict__ W1, const float* __restrict__ b1,
                      const float* __restrict__ W2, const float* __restrict__ b2,
                      const float* __restrict__ W3, const float* __restrict__ b3,
                      float* __restrict__ out) {
    __shared__ float s_pool[128];
    __shared__ float s_lat[32];
    __shared__ float s_h[128];
    int g = blockIdx.x;
    int tid = threadIdx.x;

    s_pool[tid] = g_pool[g * 128 + tid];
    __syncthreads();

    if (tid < 32) {
        float a = __ldg(b1 + tid);
        for (int i = 0; i < 128; i++) a += s_pool[i] * __ldg(W1 + i * 32 + tid);
        a = fmaxf(a, 0.0f);
        s_lat[tid] = a;
        out[2560 + g * 32 + tid] = a;
    }
    __syncthreads();

    {
        float a = __ldg(b2 + tid);
        for (int i = 0; i < 32; i++) a += s_lat[i] * __ldg(W2 + i * 128 + tid);
        s_h[tid] = fmaxf(a, 0.0f);
    }
    __syncthreads();

    if (tid < 40) {
        float a = __ldg(b3 + tid);
        for (int i = 0; i < 128; i++) a += s_h[i] * __ldg(W3 + i * 40 + tid);
        out[g * 40 + tid] = a;
    }
}

// ---------------- launch ----------------
extern "C" void kernel_launch(void* const* d_in, const int* in_sizes, int n_in,
                              void* d_out, int out_size) {
    const float* x     = (const float*)d_in[0];
    const int*   ei    = (const int*)d_in[1];
    const int*   batch = (const int*)d_in[2];
    const float *Wq1 = (const float*)d_in[3],  *bq1 = (const float*)d_in[4];
    const float *Wk1 = (const float*)d_in[5],  *bk1 = (const float*)d_in[6];
    const float *Wv1 = (const float*)d_in[7],  *bv1 = (const float*)d_in[8];
    const float *Ws1 = (const float*)d_in[9],  *bs1 = (const float*)d_in[10];
    const float *Wq2 = (const float*)d_in[11], *bq2 = (const float*)d_in[12];
    const float *Wk2 = (const float*)d_in[13], *bk2 = (const float*)d_in[14];
    const float *Wv2 = (const float*)d_in[15], *bv2 = (const float*)d_in[16];
    const float *Ws2 = (const float*)d_in[17], *bs2 = (const float*)d_in[18];
    const float *W1  = (const float*)d_in[19], *b1  = (const float*)d_in[20];
    const float *W2  = (const float*)d_in[21], *b2  = (const float*)d_in[22];
    const float *W3  = (const float*)d_in[23], *b3  = (const float*)d_in[24];
    float* out = (float*)d_out;

    // one-time side stream + fork/join events (host-side resources only)
    static cudaStream_t s_side = nullptr;
    static cudaEvent_t ev_fork = nullptr, ev_join = nullptr;
    if (s_side == nullptr) {
        cudaStreamCreateWithFlags(&s_side, cudaStreamNonBlocking);
        cudaEventCreateWithFlags(&ev_fork, cudaEventDisableTiming);
        cudaEventCreateWithFlags(&ev_join, cudaEventDisableTiming);
    }

    const int PAIR_NODE_BLOCKS = ((N_NODES / 2) * 32 + 255) / 256;  // 2 nodes/warp

    // fork: CSR build on side stream
    cudaEventRecord(ev_fork, 0);
    cudaStreamWaitEvent(s_side, ev_fork, 0);
    k_hist<<<(N_EDGES / 4 + 255) / 256, 256, 0, s_side>>>(ei);
    k_scan<<<1, 1024, 0, s_side>>>();
    k_scatter<<<(N_EDGES / 4 + 255) / 256, 256, 0, s_side>>>(ei);
    cudaEventRecord(ev_join, s_side);

    // main stream: node-parallel work that doesn't need the CSR
    k_l1_qkv<<<(N_NODES * 64 + 255) / 256, 256>>>(x, Wq1, bq1, Wk1, bk1, Wv1, bv1, Ws1, bs1);
    k_init_pool<<<(N_GRAPHS * 128 + 255) / 256, 256>>>();

    // join
    cudaStreamWaitEvent(0, ev_join, 0);

    // layer 1 edges
    k_edge1<<<PAIR_NODE_BLOCKS, 256>>>();

    // layer 2 (tensor-core GEMM: 782 row-tiles x 4 matrices)
    k_l2_qkv<<<dim3((N_NODES + 127) / 128, 4), 256>>>(Wq2, bq2, Wk2, bk2, Wv2, bv2, Ws2, bs2);
    k_edge2<<<PAIR_NODE_BLOCKS, 256>>>();
    k_pool<<<N_NODES / 32, 128>>>(batch);

    // head: one block per graph
    k_mlp<<<N_GRAPHS, 128>>>(W1, b1, W2, b2, W3, b3, out);

    // re-zero degree array for the next call (off the critical path)
    k_zero_deg<<<(N_NODES + 255) / 256, 256>>>();
}